// round 17
// baseline (speedup 1.0000x reference)
#include <cuda_runtime.h>

#define TPB 64            // 2 independent warps per CTA
#define IMG_H 512
#define IMG_W 512
#define BAND 64           // emit rows per band (8*64 = 512, exact)
#define N_ITERS 72        // 64 emit + 8 halo, multiple of 12 (ring period)
#define N_BLOCKS 2048     // grid (256 x 8)

__device__ double g_acc = 0.0;
__device__ unsigned int g_count = 0;

typedef unsigned long long u64;

// packed f32x2 helpers (FFMA2/FADD2 path — PTX-only on sm_103a)
#define PKF2(d, lo, hi)   asm("mov.b64 %0, {%1, %2};" : "=l"(d) : "f"(lo), "f"(hi))
#define UPKF2(lo, hi, s)  asm("mov.b64 {%0, %1}, %2;" : "=f"(lo), "=f"(hi) : "l"(s))
#define ADDF2(d, a, b)    asm("add.rn.f32x2 %0, %1, %2;" : "=l"(d) : "l"(a), "l"(b))
#define MULF2(d, a, b)    asm("mul.rn.f32x2 %0, %1, %2;" : "=l"(d) : "l"(a), "l"(b))
#define FMAF2(d, a, b, c) asm("fma.rn.f32x2 %0, %1, %2, %3;" : "=l"(d) : "l"(a), "l"(b), "l"(c))

// Load row (guarded): batched at iteration top for MLP.
#define LOAD_ROW(L_, A_, B_, H_)                                              \
    do {                                                                      \
        const int L = (L_);                                                   \
        if ((unsigned)L < (unsigned)rowEnd) {                                 \
            const float4* p = base4 + (size_t)L * (IMG_W / 4) + iA;           \
            A_ = __ldg(p); B_ = __ldg(p + 1);                                 \
            H_ = haloAct ? __ldg(p + hOff) : make_float4(0.f, 0.f, 0.f, 0.f); \
        } else {                                                              \
            A_ = B_ = H_ = make_float4(0.f, 0.f, 0.f, 0.f);                   \
        }                                                                     \
    } while (0)

// L2 prefetch of one row (clamped): no register destination, no scoreboard.
#define PREFETCH_ROW(L_)                                                      \
    do {                                                                      \
        const int Lp = min((L_), rowEnd - 1);                                 \
        const float4* pp = base4 + (size_t)Lp * (IMG_W / 4) + iA;             \
        asm volatile("prefetch.global.L2 [%0];" :: "l"(pp));                  \
    } while (0)

// Process one row. h-ring: fp32 PACKED (ulonglong2 = one LDS.128/STS.128 per
// half), depth 12, read slot (KS_+3)%12 (delay 9), write slot KS_%12.
// x-ring: packed pairs, depth 4, read-then-write slot KX_%4 (delay 4).
// S-slide and emit accumulation in packed f32x2 (exact fp32 per lane).
#define PROCESS_ROW(i_, KS_, KX_, cA_, cB_, cH_)                              \
    do {                                                                      \
        float4 vL, vR;                                                        \
        vL.x = __shfl_up_sync(0xffffffffu, cB_.x, 1);                         \
        vL.y = __shfl_up_sync(0xffffffffu, cB_.y, 1);                         \
        vL.z = __shfl_up_sync(0xffffffffu, cB_.z, 1);                         \
        vL.w = __shfl_up_sync(0xffffffffu, cB_.w, 1);                         \
        vR.x = __shfl_down_sync(0xffffffffu, cA_.x, 1);                       \
        vR.y = __shfl_down_sync(0xffffffffu, cA_.y, 1);                       \
        vR.z = __shfl_down_sync(0xffffffffu, cA_.z, 1);                       \
        vR.w = __shfl_down_sync(0xffffffffu, cA_.w, 1);                       \
        if (lane == 0)  vL = cH_;                                             \
        if (lane == 31) vR = cH_;                                             \
        float h0 = ((vL.x + vL.y) + (vL.z + vL.w))                            \
                 + ((cA_.x + cA_.y) + (cA_.z + cA_.w)) + cB_.x;               \
        float h1 = h0 - vL.x + cB_.y;                                         \
        float h2 = h1 - vL.y + cB_.z;                                         \
        float h3 = h2 - vL.z + cB_.w;                                         \
        float h4 = h3 - vL.w + vR.x;                                          \
        float h5 = h4 - cA_.x + vR.y;                                         \
        float h6 = h5 - cA_.y + vR.z;                                         \
        float h7 = h6 - cA_.z + vR.w;                                         \
        u64 qa01, qa23, qb01, qb23;                                           \
        PKF2(qa01, h0, h1);  PKF2(qa23, h2, h3);                              \
        PKF2(qb01, h4, h5);  PKF2(qb23, h6, h7);                              \
        const ulonglong2 oA = ringA[((KS_) + 3) % 12][tid];                   \
        const ulonglong2 oB = ringB[((KS_) + 3) % 12][tid];                   \
        ADDF2(Sa01, Sa01, qa01);  FMAF2(Sa01, oA.x, NEG1, Sa01);              \
        ADDF2(Sa23, Sa23, qa23);  FMAF2(Sa23, oA.y, NEG1, Sa23);              \
        ADDF2(Sb01, Sb01, qb01);  FMAF2(Sb01, oB.x, NEG1, Sb01);              \
        ADDF2(Sb23, Sb23, qb23);  FMAF2(Sb23, oB.y, NEG1, Sb23);              \
        ringA[(KS_) % 12][tid] = make_ulonglong2(qa01, qa23);                 \
        ringB[(KS_) % 12][tid] = make_ulonglong2(qb01, qb23);                 \
        const u64 xa01 = xrA01[(KX_) % 4];  /* x from row i-4, packed */      \
        const u64 xa23 = xrA23[(KX_) % 4];                                    \
        const u64 xb01 = xrB01[(KX_) % 4];                                    \
        const u64 xb23 = xrB23[(KX_) % 4];                                    \
        PKF2(xrA01[(KX_) % 4], cA_.x, cA_.y);   /* overwrite with row i */    \
        PKF2(xrA23[(KX_) % 4], cA_.z, cA_.w);                                 \
        PKF2(xrB01[(KX_) % 4], cB_.x, cB_.y);                                 \
        PKF2(xrB23[(KX_) % 4], cB_.z, cB_.w);                                 \
        if ((i_) >= 8) {                                                      \
            FMAF2(accsq2, xa01, xa01, accsq2);                                \
            FMAF2(accsq2, xa23, xa23, accsq2);                                \
            FMAF2(accsq2, xb01, xb01, accsq2);                                \
            FMAF2(accsq2, xb23, xb23, accsq2);                                \
            FMAF2(accxs2, xa01, Sa01, accxs2);                                \
            FMAF2(accxs2, xa23, Sa23, accxs2);                                \
            FMAF2(accxs2, xb01, Sb01, accxs2);                                \
            FMAF2(accxs2, xb23, Sb23, accxs2);                                \
            const u64 xs01 = (colhalf == 0) ? xa01 : xb01;                    \
            const u64 xs23 = (colhalf == 0) ? xa23 : xb23;                    \
            u64 t01, t23;                                                     \
            MULF2(t01, w01p, xs01);  FMAF2(accw2, t01, xs01, accw2);          \
            MULF2(t23, w23p, xs23);  FMAF2(accw2, t23, xs23, accw2);          \
            const int r = rowStart - 8 + (i_);                                \
            const bool rowB = (r < 4) | (r > IMG_H - 5);                      \
            if (rowB) {   /* uniform, <=8 rows per band */                    \
                float a0, a1, a2, a3, b0, b1, b2, b3, s0, s1, s2, s3;         \
                UPKF2(a0, a1, xa01);  UPKF2(a2, a3, xa23);                    \
                UPKF2(b0, b1, xb01);  UPKF2(b2, b3, xb23);                    \
                UPKF2(s0, s1, xs01);  UPKF2(s2, s3, xs23);                    \
                float rowsq = ((a0 * a0 + a1 * a1) + (a2 * a2 + a3 * a3))     \
                            + ((b0 * b0 + b1 * b1) + (b2 * b2 + b3 * b3));    \
                float roww  = ((w4.x * s0 * s0 + w4.y * s1 * s1)              \
                             + (w4.z * s2 * s2 + w4.w * s3 * s3));            \
                const float cnth = (float)(min(r, 4) + min(IMG_H - 1 - r, 4) + 1); \
                acc_c = fmaf(9.0f - cnth, fmaf(9.0f, rowsq, -roww), acc_c);   \
            }                                                                 \
        }                                                                     \
    } while (0)

__global__ void __launch_bounds__(TPB, 8) sc_main(const float* __restrict__ img,
                                                  float* __restrict__ out) {
    const int tid  = threadIdx.x;
    const int lane = tid & 31;
    const int wid  = tid >> 5;
    const int plane   = blockIdx.x;
    const int region  = blockIdx.y * 2 + wid;   // 0..15
    const int colhalf = region & 1;
    const int vband   = region >> 1;            // 0..7
    const int rowStart = vband * BAND;
    const int rowEnd   = min(IMG_H, rowStart + BAND + 4);  // last h-row + 1

    const float4* base4 = (const float4*)img + (size_t)plane * (IMG_H * (IMG_W / 4));
    const int iA = colhalf * 64 + 2 * lane;

    const bool haloAct = (lane == 0 && colhalf == 1) || (lane == 31 && colhalf == 0);
    const int  hOff    = (lane == 0) ? -1 : 2;

    const int cbase = colhalf * 256 + 8 * lane;
    const int cj = (colhalf == 0) ? cbase : cbase + 4;
    float4 w4;
    w4.x = (float)(max(4 - (cj + 0), 0) + max((cj + 0) - 507, 0));
    w4.y = (float)(max(4 - (cj + 1), 0) + max((cj + 1) - 507, 0));
    w4.z = (float)(max(4 - (cj + 2), 0) + max((cj + 2) - 507, 0));
    w4.w = (float)(max(4 - (cj + 3), 0) + max((cj + 3) - 507, 0));
    u64 w01p, w23p, NEG1;
    PKF2(w01p, w4.x, w4.y);
    PKF2(w23p, w4.z, w4.w);
    PKF2(NEG1, -1.0f, -1.0f);

    // fp32 PACKED h ring, depth 12; 16B/slot per half -> LDS.128/STS.128
    __shared__ ulonglong2 ringA[12][TPB];
    __shared__ ulonglong2 ringB[12][TPB];
#pragma unroll
    for (int i = 0; i < 12; i++) {
        ringA[i][tid] = make_ulonglong2(0ull, 0ull);
        ringB[i][tid] = make_ulonglong2(0ull, 0ull);
    }

    // x ring, packed pairs, depth 4, read-then-write (delay 4)
    u64 xrA01[4], xrA23[4], xrB01[4], xrB23[4];
#pragma unroll
    for (int i = 0; i < 4; i++) {
        xrA01[i] = 0ull; xrA23[i] = 0ull; xrB01[i] = 0ull; xrB23[i] = 0ull;
    }
    u64 Sa01 = 0ull, Sa23 = 0ull, Sb01 = 0ull, Sb23 = 0ull;   // vertical 9-sum
    u64 accsq2 = 0ull, accxs2 = 0ull, accw2 = 0ull;
    float acc_c = 0.f;

    // pipeline: rows i and i+1 resident, rows i+2/i+3 loaded at iteration top
    float4 c0A, c0B, c0H, c1A, c1B, c1H;
    LOAD_ROW(rowStart - 4, c0A, c0B, c0H);
    LOAD_ROW(rowStart - 3, c1A, c1B, c1H);
    PREFETCH_ROW(rowStart - 2);
    PREFETCH_ROW(rowStart - 1);
    PREFETCH_ROW(rowStart);
    PREFETCH_ROW(rowStart + 1);

    for (int it = 0; it < N_ITERS / 12; ++it) {
#pragma unroll
        for (int kk = 0; kk < 6; ++kk) {
            const int i0 = it * 12 + 2 * kk;

            // next row pair (front-batched LDGs) + L2 prefetch 6 rows ahead
            float4 n0A, n0B, n0H, n1A, n1B, n1H;
            LOAD_ROW(rowStart - 2 + i0, n0A, n0B, n0H);
            LOAD_ROW(rowStart - 1 + i0, n1A, n1B, n1H);
            PREFETCH_ROW(rowStart + 2 + i0);
            PREFETCH_ROW(rowStart + 3 + i0);

            PROCESS_ROW(i0,     2 * kk,     2 * kk,     c0A, c0B, c0H);
            PROCESS_ROW(i0 + 1, 2 * kk + 1, 2 * kk + 1, c1A, c1B, c1H);

            c0A = n0A; c0B = n0B; c0H = n0H;
            c1A = n1A; c1B = n1B; c1H = n1H;
        }
    }

    // unpack packed accumulators and combine
    float q0, q1, x0, x1, v0, v1;
    UPKF2(q0, q1, accsq2);
    UPKF2(x0, x1, accxs2);
    UPKF2(v0, v1, accw2);
    const float acc_sq = q0 + q1;
    const float acc_xs = x0 + x1;
    const float acc_w  = v0 + v1;
    float acc = fmaf(162.0f, acc_sq, fmaf(-2.0f, acc_xs, -fmaf(9.0f, acc_w, acc_c)));

    // warp reduce -> CTA reduce -> one atomic per CTA; last CTA finalizes
#pragma unroll
    for (int off = 16; off; off >>= 1) acc += __shfl_down_sync(0xffffffffu, acc, off);
    __shared__ float wsum[2];
    if (lane == 0) wsum[wid] = acc;
    __syncthreads();
    if (tid == 0) {
        atomicAdd(&g_acc, (double)(wsum[0] + wsum[1]));
        __threadfence();
        unsigned int t = atomicAdd(&g_count, 1u);
        if (t == N_BLOCKS - 1) {
            out[0] = (float)(g_acc * 0.125);   // mean over batch of 8
            g_acc = 0.0;
            g_count = 0u;
        }
    }
}

extern "C" void kernel_launch(void* const* d_in, const int* in_sizes, int n_in,
                              void* d_out, int out_size) {
    const float* img = (const float*)d_in[0];
    dim3 grid(256, 8);          // 2048 CTAs = N_BLOCKS
    sc_main<<<grid, TPB>>>(img, (float*)d_out);
}